// round 16
// baseline (speedup 1.0000x reference)
#include <cuda_runtime.h>
#include <cuda_fp16.h>
#include <math.h>
#include <stdint.h>

// Problem constants
#define NB 32
#define NS 1024
#define NT 256
#define NBS 32768          // NB*NS rows
#define KCAT 1024          // 4*NT concatenated K (shift segments)

// Static device scratch (allocation-free rule: __device__ globals)
__device__ __half g_Ph[(size_t)NBS * NT];    // fp16 softmax(q)   16.8 MB
__device__ __half g_BT[NT * KCAT];           // Bcat2^T[n][k], K-major 0.5 MB

__constant__ int c_shift[4] = {-1, -2, 1, 2};

// ---------------------------------------------------------------------------
// Build Bcat2^T (K-major rows): BT[n][k], n in [0,256), k in [0,1024)
// segment j = k>>8, kk = k&255:
//   j=0: T0[kk][n]  j=1: T1[kk][n]  j=2: T0[n][kk]  j=3: T1[n][kk]
// transitions layout: [2, 256, 256] row-major
// ---------------------------------------------------------------------------
__global__ void build_b_kernel(const float* __restrict__ trans) {
    int idx = blockIdx.x * blockDim.x + threadIdx.x;   // 0 .. 262143
    int n = idx >> 10;         // 0..255
    int k = idx & 1023;        // 0..1023
    int seg = k >> 8;
    int kk = k & 255;
    float v;
    if (seg == 0)      v = trans[kk * 256 + n];
    else if (seg == 1) v = trans[65536 + kk * 256 + n];
    else if (seg == 2) v = trans[n * 256 + kk];
    else               v = trans[65536 + n * 256 + kk];
    g_BT[n * KCAT + k] = __float2half_rn(v);
}

// ---------------------------------------------------------------------------
// init P: Ph = softmax(unary*mask) per row (warp per row)
// ---------------------------------------------------------------------------
__global__ void __launch_bounds__(256) init_p_kernel(
    const float* __restrict__ unary_score,
    const float* __restrict__ mask)
{
    int warp = threadIdx.x >> 5;
    int lane = threadIdx.x & 31;
    int row = blockIdx.x * 8 + warp;
    float m = mask[row];
    size_t base = (size_t)row * NT + lane;

    float q[8];
#pragma unroll
    for (int j = 0; j < 8; ++j) q[j] = unary_score[base + j * 32] * m;

    float mx = q[0];
#pragma unroll
    for (int j = 1; j < 8; ++j) mx = fmaxf(mx, q[j]);
#pragma unroll
    for (int o = 16; o; o >>= 1) mx = fmaxf(mx, __shfl_xor_sync(0xffffffffu, mx, o));
    float e[8], sum = 0.0f;
#pragma unroll
    for (int j = 0; j < 8; ++j) { e[j] = __expf(q[j] - mx); sum += e[j]; }
#pragma unroll
    for (int o = 16; o; o >>= 1) sum += __shfl_xor_sync(0xffffffffu, sum, o);
    float rinv = __frcp_rn(sum);
#pragma unroll
    for (int j = 0; j < 8; ++j)
        g_Ph[base + j * 32] = __float2half_rn(e[j] * rinv);
}

// ---------------------------------------------------------------------------
// Fused GEMM + combine: one CTA owns a full 128x256 output block.
// msg = Acat[128,1024] @ Bcat2[1024,256]; Acat[row][k] = P[row+shift(k>>8)][k&255]
// Then q = (unary*mask + msg + boundary)*mask; mode 1 -> softmax -> Ph,
// mode 2 -> write q to out.
// 8 warps (2m x 4n), warp tile 64x64. K in 32 chunks of 32 halves (64B rows).
// 2-stage pipeline: stage = A 8KB + B 16KB = 24KB; 2 stages = 48KB.
// Masked tiles (s0 >= len): mode1 skip (Ph uniform from init, constant);
// mode2 write zeros.
// ---------------------------------------------------------------------------
#define A_BYTES 8192                     // 128 rows x 64 B
#define B_BYTES 16384                    // 256 rows x 64 B
#define STAGE_BYTES (A_BYTES + B_BYTES)  // 24 KB
#define GEMM_SMEM (2 * STAGE_BYTES)      // 48 KB
#define NCHUNK 32

__device__ __forceinline__ void mma16816(float* d, uint32_t a0, uint32_t a1,
                                         uint32_t a2, uint32_t a3,
                                         uint32_t b0, uint32_t b1) {
    asm volatile(
        "mma.sync.aligned.m16n8k16.row.col.f32.f16.f16.f32 "
        "{%0,%1,%2,%3}, {%4,%5,%6,%7}, {%8,%9}, {%0,%1,%2,%3};"
        : "+f"(d[0]), "+f"(d[1]), "+f"(d[2]), "+f"(d[3])
        : "r"(a0), "r"(a1), "r"(a2), "r"(a3), "r"(b0), "r"(b1));
}

__device__ __forceinline__ void ldsm_x4(uint32_t addr, uint32_t& r0, uint32_t& r1,
                                        uint32_t& r2, uint32_t& r3) {
    asm volatile("ldmatrix.sync.aligned.m8n8.x4.shared.b16 {%0,%1,%2,%3}, [%4];"
                 : "=r"(r0), "=r"(r1), "=r"(r2), "=r"(r3) : "r"(addr));
}

__device__ __forceinline__ void cp16z(uint32_t dst, const void* src, uint32_t srcsz) {
    asm volatile("cp.async.cg.shared.global [%0], [%1], 16, %2;"
                 :: "r"(dst), "l"(src), "r"(srcsz) : "memory");
}

__device__ __forceinline__ uint32_t sw32(uint32_t row) {   // 64B-row swizzle
    return ((row >> 1) & 3u) << 4;
}

// A-tile: 128 rows x 64B from shifted P (zero-fill out of range). 256 threads.
__device__ __forceinline__ void copy_tileA_async(uint32_t dst, int m0, int c, int tid) {
    int k0 = c * 32;
    int seg = k0 >> 8;
    int kk0 = k0 & 255;
    int shift = c_shift[seg];
#pragma unroll
    for (int p = 0; p < 2; ++p) {
        int u = tid + p * 256;          // 0..511
        int row = u >> 2;               // 0..127
        uint32_t col = (uint32_t)((u & 3) * 16);
        int gr = m0 + row;
        int s = gr & (NS - 1);
        uint32_t ok = ((unsigned)(s + shift) < (unsigned)NS) ? 16u : 0u;
        const __half* sp = ok ? (g_Ph + (size_t)(gr + shift) * NT + kk0) : g_Ph;
        cp16z(dst + (uint32_t)(row * 64) + (col ^ sw32((uint32_t)row)),
              (const char*)sp + col, ok);
    }
}

// B-tile: 256 rows x 64B from g_BT. 256 threads.
__device__ __forceinline__ void copy_tileB_async(uint32_t dst, int c, int tid) {
    int k0 = c * 32;
#pragma unroll
    for (int p = 0; p < 4; ++p) {
        int u = tid + p * 256;          // 0..1023
        int row = u >> 2;               // 0..255
        uint32_t col = (uint32_t)((u & 3) * 16);
        const void* src = (const char*)(g_BT + (size_t)row * KCAT + k0) + col;
        cp16z(dst + (uint32_t)(row * 64) + (col ^ sw32((uint32_t)row)), src, 16u);
    }
}

__device__ __forceinline__ void prefetch_chunk(uint32_t sb, int c, int m0, int tid) {
    uint32_t st = sb + (uint32_t)(c & 1) * STAGE_BYTES;
    copy_tileA_async(st, m0, c, tid);
    copy_tileB_async(st + A_BYTES, c, tid);
    asm volatile("cp.async.commit_group;" ::: "memory");
}

// One pass over a 32-half K chunk. Warp tile 64x64: 4 m-frags x 8 n-frags.
__device__ __forceinline__ void mma_pass32(uint32_t aB, uint32_t bB,
                                           float acc[4][8][4],
                                           int wm, int wn, int lane) {
    int lr = lane & 7;
    int quad = lane >> 3;
    int rlow = (quad & 1) * 8 + lr;
    int khb = (quad >> 1) * 16;

#pragma unroll
    for (int ks = 0; ks < 2; ++ks) {
        uint32_t kb = (uint32_t)(ks * 32 + khb);
        uint32_t af[4][4];
#pragma unroll
        for (int mf = 0; mf < 4; ++mf) {
            uint32_t row = (uint32_t)(wm * 64 + mf * 16 + rlow);
            uint32_t addr = aB + row * 64 + (kb ^ sw32(row));
            ldsm_x4(addr, af[mf][0], af[mf][1], af[mf][2], af[mf][3]);
        }
        uint32_t bf[8][2];
#pragma unroll
        for (int i = 0; i < 4; ++i) {
            uint32_t row = (uint32_t)(wn * 64 + i * 16 + rlow);
            uint32_t addr = bB + row * 64 + (kb ^ sw32(row));
            ldsm_x4(addr, bf[2 * i][0], bf[2 * i + 1][0],
                    bf[2 * i][1], bf[2 * i + 1][1]);
        }
#pragma unroll
        for (int mf = 0; mf < 4; ++mf)
#pragma unroll
            for (int nf = 0; nf < 8; ++nf)
                mma16816(acc[mf][nf], af[mf][0], af[mf][1], af[mf][2],
                         af[mf][3], bf[nf][0], bf[nf][1]);
    }
}

__global__ void __launch_bounds__(256, 1) gemm_fused_kernel(
    const float* __restrict__ unary_score,
    const float* __restrict__ mask,
    const float* __restrict__ start_t,   // [2,256]
    const float* __restrict__ end_t,     // [2,256]
    const int*   __restrict__ lengths,   // [32]
    float* __restrict__ out,
    int mode)                            // 1: softmax->Ph, 2: q->out
{
    extern __shared__ char smem[];
    uint32_t sb = (uint32_t)__cvta_generic_to_shared(smem);

    int tid  = threadIdx.x;
    int m0 = blockIdx.x * 128;
    int s0 = m0 & (NS - 1);
    int b  = m0 >> 10;
    int len = __ldg(&lengths[b]);

    if (s0 >= len) {
        // fully masked tile: q = 0. mode1: Ph already uniform (constant
        // across iterations, set by init_p). mode2: out must be zeroed.
        if (mode == 2) {
            float4 z = make_float4(0.f, 0.f, 0.f, 0.f);
            float4* o = (float4*)(out + (size_t)m0 * NT);
            for (int i = tid; i < 128 * NT / 4; i += 256) o[i] = z;
        }
        return;
    }

    int wid  = tid >> 5;
    int lane = tid & 31;
    int wm = wid & 1;          // 0..1 : 64-row half
    int wn = wid >> 1;         // 0..3 : 64-col quarter
    int g  = lane >> 2;        // 0..7
    int tg = lane & 3;         // 0..3

    float acc[4][8][4];
#pragma unroll
    for (int i = 0; i < 4; i++)
#pragma unroll
        for (int j = 0; j < 8; j++)
#pragma unroll
            for (int r = 0; r < 4; r++) acc[i][j][r] = 0.0f;

    prefetch_chunk(sb, 0, m0, tid);

    for (int c = 0; c < NCHUNK; ++c) {
        if (c + 1 < NCHUNK) {
            // stage (c+1)&1 was freed by the barrier at end of iter c-1
            prefetch_chunk(sb, c + 1, m0, tid);
            asm volatile("cp.async.wait_group 1;" ::: "memory");
        } else {
            asm volatile("cp.async.wait_group 0;" ::: "memory");
        }
        __syncthreads();                 // publish chunk c

        uint32_t cur = sb + (uint32_t)(c & 1) * STAGE_BYTES;
        mma_pass32(cur, cur + A_BYTES, acc, wm, wn, lane);
        __syncthreads();                 // free stage c&1
    }

    // ---------------- fused epilogue ----------------
    // thread's rows: rl(i) = wm*64 + (i>>1)*16 + g + (i&1)*8, i = 0..7
    // thread's cols: col(nf) = wn*64 + nf*8 + 2*tg (+1)
    float rowm[8], rowv[8];

#pragma unroll
    for (int i = 0; i < 8; ++i) {
        int mf = i >> 1, rsel = i & 1;
        int rl = wm * 64 + mf * 16 + g + rsel * 8;
        int gr = m0 + rl;
        int s = gr & (NS - 1);
        float m = mask[gr];
        const float* bnd = 0;
        if (s < 2)            bnd = start_t + s * 256;
        else if (s == len - 1) bnd = end_t;
        else if (s == len - 2) bnd = end_t + 256;

        float mx = -3.0e38f;
#pragma unroll
        for (int nf = 0; nf < 8; ++nf) {
            int col = wn * 64 + nf * 8 + tg * 2;
            float2 u = *(const float2*)(unary_score + (size_t)gr * NT + col);
            float q0 = u.x * m + acc[mf][nf][rsel * 2 + 0];
            float q1 = u.y * m + acc[mf][nf][rsel * 2 + 1];
            if (bnd) { q0 += bnd[col]; q1 += bnd[col + 1]; }
            q0 *= m; q1 *= m;
            acc[mf][nf][rsel * 2 + 0] = q0;
            acc[mf][nf][rsel * 2 + 1] = q1;
            mx = fmaxf(mx, fmaxf(q0, q1));
        }
        rowm[i] = mx;
    }

    if (mode == 2) {
#pragma unroll
        for (int i = 0; i < 8; ++i) {
            int mf = i >> 1, rsel = i & 1;
            int gr = m0 + wm * 64 + mf * 16 + g + rsel * 8;
#pragma unroll
            for (int nf = 0; nf < 8; ++nf) {
                int col = wn * 64 + nf * 8 + tg * 2;
                *(float2*)(out + (size_t)gr * NT + col) =
                    make_float2(acc[mf][nf][rsel * 2], acc[mf][nf][rsel * 2 + 1]);
            }
        }
        return;
    }

    // softmax across 256 cols: quad reduce (tg) then cross-warp (wn) via smem
    float* red0 = (float*)smem;          // [4][128]
    float* red1 = (float*)smem + 512;    // [4][128]

#pragma unroll
    for (int i = 0; i < 8; ++i) {
        float mx = rowm[i];
        mx = fmaxf(mx, __shfl_xor_sync(0xffffffffu, mx, 1));
        mx = fmaxf(mx, __shfl_xor_sync(0xffffffffu, mx, 2));
        rowm[i] = mx;
    }
    if (tg == 0) {
#pragma unroll
        for (int i = 0; i < 8; ++i) {
            int rl = wm * 64 + (i >> 1) * 16 + g + (i & 1) * 8;
            red0[wn * 128 + rl] = rowm[i];
        }
    }
    __syncthreads();
#pragma unroll
    for (int i = 0; i < 8; ++i) {
        int rl = wm * 64 + (i >> 1) * 16 + g + (i & 1) * 8;
        float mx = fmaxf(fmaxf(red0[rl], red0[128 + rl]),
                         fmaxf(red0[256 + rl], red0[384 + rl]));
        rowm[i] = mx;
        // exp in place, accumulate sum
        int mf = i >> 1, rsel = i & 1;
        float sum = 0.0f;
#pragma unroll
        for (int nf = 0; nf < 8; ++nf) {
            float e0 = __expf(acc[mf][nf][rsel * 2 + 0] - mx);
            float e1 = __expf(acc[mf][nf][rsel * 2 + 1] - mx);
            acc[mf][nf][rsel * 2 + 0] = e0;
            acc[mf][nf][rsel * 2 + 1] = e1;
            sum += e0 + e1;
        }
        sum += __shfl_xor_sync(0xffffffffu, sum, 1);
        sum += __shfl_xor_sync(0xffffffffu, sum, 2);
        rowv[i] = sum;
    }
    if (tg == 0) {
#pragma unroll
        for (int i = 0; i < 8; ++i) {
            int rl = wm * 64 + (i >> 1) * 16 + g + (i & 1) * 8;
            red1[wn * 128 + rl] = rowv[i];
        }
    }
    __syncthreads();
#pragma unroll
    for (int i = 0; i < 8; ++i) {
        int rl = wm * 64 + (i >> 1) * 16 + g + (i & 1) * 8;
        float sum = red1[rl] + red1[128 + rl] + red1[256 + rl] + red1[384 + rl];
        float rinv = __frcp_rn(sum);
        int mf = i >> 1, rsel = i & 1;
        int gr = m0 + rl;
#pragma unroll
        for (int nf = 0; nf < 8; ++nf) {
            int col = wn * 64 + nf * 8 + tg * 2;
            *(__half2*)(g_Ph + (size_t)gr * NT + col) =
                __floats2half2_rn(acc[mf][nf][rsel * 2] * rinv,
                                  acc[mf][nf][rsel * 2 + 1] * rinv);
        }
    }
}

// ---------------------------------------------------------------------------
// Input order: token_feats, unary_score, mask, transitions,
//              start_transitions, end_transitions, lengths
// ---------------------------------------------------------------------------
extern "C" void kernel_launch(void* const* d_in, const int* in_sizes, int n_in,
                              void* d_out, int out_size) {
    const float* unary   = (const float*)d_in[1];
    const float* mask    = (const float*)d_in[2];
    const float* trans   = (const float*)d_in[3];
    const float* start_t = (const float*)d_in[4];
    const float* end_t   = (const float*)d_in[5];
    const int*   lengths = (const int*)d_in[6];
    float* out = (float*)d_out;

    build_b_kernel<<<1024, 256>>>(trans);
    init_p_kernel<<<NBS / 8, 256>>>(unary, mask);

    for (int it = 0; it < 3; ++it) {
        int mode = (it == 2) ? 2 : 1;
        gemm_fused_kernel<<<NBS / 128, 256, GEMM_SMEM>>>(
            unary, mask, start_t, end_t, lengths, out, mode);
    }
}

// round 17
// speedup vs baseline: 1.2742x; 1.2742x over previous
#include <cuda_runtime.h>
#include <cuda_fp16.h>
#include <math.h>
#include <stdint.h>

// Problem constants
#define NB 32
#define NS 1024
#define NT 256
#define NBS 32768          // NB*NS rows
#define KCAT 1024          // 4*NT concatenated K (shift segments)

// Static device scratch (allocation-free rule: __device__ globals)
__device__ __half g_Ph[(size_t)NBS * NT];    // fp16 softmax(q)   16.8 MB
__device__ __half g_BT[NT * KCAT];           // Bcat2^T[n][k], K-major 0.5 MB

__constant__ int c_shift[4] = {-1, -2, 1, 2};

// ---------------------------------------------------------------------------
// Build Bcat2^T (K-major rows): BT[n][k], n in [0,256), k in [0,1024)
// segment j = k>>8, kk = k&255:
//   j=0: T0[kk][n]  j=1: T1[kk][n]  j=2: T0[n][kk]  j=3: T1[n][kk]
// ---------------------------------------------------------------------------
__global__ void build_b_kernel(const float* __restrict__ trans) {
    int idx = blockIdx.x * blockDim.x + threadIdx.x;   // 0 .. 262143
    int n = idx >> 10;         // 0..255
    int k = idx & 1023;        // 0..1023
    int seg = k >> 8;
    int kk = k & 255;
    float v;
    if (seg == 0)      v = trans[kk * 256 + n];
    else if (seg == 1) v = trans[65536 + kk * 256 + n];
    else if (seg == 2) v = trans[n * 256 + kk];
    else               v = trans[65536 + n * 256 + kk];
    g_BT[n * KCAT + k] = __float2half_rn(v);
}

// ---------------------------------------------------------------------------
// init P: Ph = softmax(unary*mask) per row (warp per row)
// ---------------------------------------------------------------------------
__global__ void __launch_bounds__(256) init_p_kernel(
    const float* __restrict__ unary_score,
    const float* __restrict__ mask)
{
    int warp = threadIdx.x >> 5;
    int lane = threadIdx.x & 31;
    int row = blockIdx.x * 8 + warp;
    float m = mask[row];
    size_t base = (size_t)row * NT + lane;

    float q[8];
#pragma unroll
    for (int j = 0; j < 8; ++j) q[j] = unary_score[base + j * 32] * m;

    float mx = q[0];
#pragma unroll
    for (int j = 1; j < 8; ++j) mx = fmaxf(mx, q[j]);
#pragma unroll
    for (int o = 16; o; o >>= 1) mx = fmaxf(mx, __shfl_xor_sync(0xffffffffu, mx, o));
    float e[8], sum = 0.0f;
#pragma unroll
    for (int j = 0; j < 8; ++j) { e[j] = __expf(q[j] - mx); sum += e[j]; }
#pragma unroll
    for (int o = 16; o; o >>= 1) sum += __shfl_xor_sync(0xffffffffu, sum, o);
    float rinv = __frcp_rn(sum);
#pragma unroll
    for (int j = 0; j < 8; ++j)
        g_Ph[base + j * 32] = __float2half_rn(e[j] * rinv);
}

// ---------------------------------------------------------------------------
// Fused GEMM + combine: one CTA owns a full 64x256 output block (512 CTAs).
// msg = Acat[64,1024] @ Bcat2[1024,256]; Acat[row][k] = P[row+shift(k>>8)][k&255]
// q = (unary*mask + msg + boundary)*mask; mode 1 -> softmax -> Ph,
// mode 2 -> q -> out.
// 8 warps (2m x 4n), warp tile 32x64 (acc 64 regs -> 2 CTAs/SM).
// K in 32 chunks of 32 halves (64B rows). 2-stage pipeline:
// stage = A 4KB + B 16KB = 20KB; 2 stages = 40KB.
// Masked tiles (s0 >= len) skip (mode1: Ph uniform/constant; mode2: zeros).
// ---------------------------------------------------------------------------
#define A_BYTES 4096                     // 64 rows x 64 B
#define B_BYTES 16384                    // 256 rows x 64 B
#define STAGE_BYTES (A_BYTES + B_BYTES)  // 20 KB
#define GEMM_SMEM (2 * STAGE_BYTES)      // 40 KB
#define NCHUNK 32

__device__ __forceinline__ void mma16816(float* d, uint32_t a0, uint32_t a1,
                                         uint32_t a2, uint32_t a3,
                                         uint32_t b0, uint32_t b1) {
    asm volatile(
        "mma.sync.aligned.m16n8k16.row.col.f32.f16.f16.f32 "
        "{%0,%1,%2,%3}, {%4,%5,%6,%7}, {%8,%9}, {%0,%1,%2,%3};"
        : "+f"(d[0]), "+f"(d[1]), "+f"(d[2]), "+f"(d[3])
        : "r"(a0), "r"(a1), "r"(a2), "r"(a3), "r"(b0), "r"(b1));
}

__device__ __forceinline__ void ldsm_x4(uint32_t addr, uint32_t& r0, uint32_t& r1,
                                        uint32_t& r2, uint32_t& r3) {
    asm volatile("ldmatrix.sync.aligned.m8n8.x4.shared.b16 {%0,%1,%2,%3}, [%4];"
                 : "=r"(r0), "=r"(r1), "=r"(r2), "=r"(r3) : "r"(addr));
}

__device__ __forceinline__ void cp16z(uint32_t dst, const void* src, uint32_t srcsz) {
    asm volatile("cp.async.cg.shared.global [%0], [%1], 16, %2;"
                 :: "r"(dst), "l"(src), "r"(srcsz) : "memory");
}

__device__ __forceinline__ uint32_t sw32(uint32_t row) {   // 64B-row swizzle
    return ((row >> 1) & 3u) << 4;
}

// A-tile: 64 rows x 64B from shifted P (zero-fill out of range). 256 threads.
__device__ __forceinline__ void copy_tileA_async(uint32_t dst, int m0, int c, int tid) {
    int k0 = c * 32;
    int seg = k0 >> 8;
    int kk0 = k0 & 255;
    int shift = c_shift[seg];
    int row = tid >> 2;                 // 0..63
    uint32_t col = (uint32_t)((tid & 3) * 16);
    int gr = m0 + row;
    int s = gr & (NS - 1);
    uint32_t ok = ((unsigned)(s + shift) < (unsigned)NS) ? 16u : 0u;
    const __half* sp = ok ? (g_Ph + (size_t)(gr + shift) * NT + kk0) : g_Ph;
    cp16z(dst + (uint32_t)(row * 64) + (col ^ sw32((uint32_t)row)),
          (const char*)sp + col, ok);
}

// B-tile: 256 rows x 64B from g_BT. 256 threads.
__device__ __forceinline__ void copy_tileB_async(uint32_t dst, int c, int tid) {
    int k0 = c * 32;
#pragma unroll
    for (int p = 0; p < 4; ++p) {
        int u = tid + p * 256;          // 0..1023
        int row = u >> 2;               // 0..255
        uint32_t col = (uint32_t)((u & 3) * 16);
        const void* src = (const char*)(g_BT + (size_t)row * KCAT + k0) + col;
        cp16z(dst + (uint32_t)(row * 64) + (col ^ sw32((uint32_t)row)), src, 16u);
    }
}

__device__ __forceinline__ void prefetch_chunk(uint32_t sb, int c, int m0, int tid) {
    uint32_t st = sb + (uint32_t)(c & 1) * STAGE_BYTES;
    copy_tileA_async(st, m0, c, tid);
    copy_tileB_async(st + A_BYTES, c, tid);
    asm volatile("cp.async.commit_group;" ::: "memory");
}

// One pass over a 32-half K chunk. Warp tile 32x64: 2 m-frags x 8 n-frags.
__device__ __forceinline__ void mma_pass32(uint32_t aB, uint32_t bB,
                                           float acc[2][8][4],
                                           int wm, int wn, int lane) {
    int lr = lane & 7;
    int quad = lane >> 3;
    int rlow = (quad & 1) * 8 + lr;
    int khb = (quad >> 1) * 16;

#pragma unroll
    for (int ks = 0; ks < 2; ++ks) {
        uint32_t kb = (uint32_t)(ks * 32 + khb);
        uint32_t af[2][4];
#pragma unroll
        for (int mf = 0; mf < 2; ++mf) {
            uint32_t row = (uint32_t)(wm * 32 + mf * 16 + rlow);
            uint32_t addr = aB + row * 64 + (kb ^ sw32(row));
            ldsm_x4(addr, af[mf][0], af[mf][1], af[mf][2], af[mf][3]);
        }
        uint32_t bf[8][2];
#pragma unroll
        for (int i = 0; i < 4; ++i) {
            uint32_t row = (uint32_t)(wn * 64 + i * 16 + rlow);
            uint32_t addr = bB + row * 64 + (kb ^ sw32(row));
            ldsm_x4(addr, bf[2 * i][0], bf[2 * i + 1][0],
                    bf[2 * i][1], bf[2 * i + 1][1]);
        }
#pragma unroll
        for (int mf = 0; mf < 2; ++mf)
#pragma unroll
            for (int nf = 0; nf < 8; ++nf)
                mma16816(acc[mf][nf], af[mf][0], af[mf][1], af[mf][2],
                         af[mf][3], bf[nf][0], bf[nf][1]);
    }
}

__global__ void __launch_bounds__(256, 2) gemm_fused_kernel(
    const float* __restrict__ unary_score,
    const float* __restrict__ mask,
    const float* __restrict__ start_t,   // [2,256]
    const float* __restrict__ end_t,     // [2,256]
    const int*   __restrict__ lengths,   // [32]
    float* __restrict__ out,
    int mode)                            // 1: softmax->Ph, 2: q->out
{
    extern __shared__ char smem[];
    uint32_t sb = (uint32_t)__cvta_generic_to_shared(smem);

    int tid  = threadIdx.x;
    int m0 = blockIdx.x * 64;
    int s0 = m0 & (NS - 1);
    int b  = m0 >> 10;
    int len = __ldg(&lengths[b]);

    if (s0 >= len) {
        // fully masked tile: q = 0. mode1: Ph already uniform (constant
        // across iterations, set by init_p). mode2: out must be zeroed.
        if (mode == 2) {
            float4 z = make_float4(0.f, 0.f, 0.f, 0.f);
            float4* o = (float4*)(out + (size_t)m0 * NT);
            for (int i = tid; i < 64 * NT / 4; i += 256) o[i] = z;
        }
        return;
    }

    int wid  = tid >> 5;
    int lane = tid & 31;
    int wm = wid & 1;          // 0..1 : 32-row half
    int wn = wid >> 1;         // 0..3 : 64-col quarter
    int g  = lane >> 2;        // 0..7
    int tg = lane & 3;         // 0..3

    float acc[2][8][4];
#pragma unroll
    for (int i = 0; i < 2; i++)
#pragma unroll
        for (int j = 0; j < 8; j++)
#pragma unroll
            for (int r = 0; r < 4; r++) acc[i][j][r] = 0.0f;

    prefetch_chunk(sb, 0, m0, tid);

    for (int c = 0; c < NCHUNK; ++c) {
        if (c + 1 < NCHUNK) {
            prefetch_chunk(sb, c + 1, m0, tid);
            asm volatile("cp.async.wait_group 1;" ::: "memory");
        } else {
            asm volatile("cp.async.wait_group 0;" ::: "memory");
        }
        __syncthreads();                 // publish chunk c

        uint32_t cur = sb + (uint32_t)(c & 1) * STAGE_BYTES;
        mma_pass32(cur, cur + A_BYTES, acc, wm, wn, lane);
        __syncthreads();                 // free stage c&1
    }

    // ---------------- fused epilogue ----------------
    // thread's rows: rl(i) = wm*32 + (i>>1)*16 + g + (i&1)*8, i = 0..3
    // thread's cols: col(nf) = wn*64 + nf*8 + 2*tg (+1)
    float rowm[4], rowv[4];

#pragma unroll
    for (int i = 0; i < 4; ++i) {
        int mf = i >> 1, rsel = i & 1;
        int rl = wm * 32 + mf * 16 + g + rsel * 8;
        int gr = m0 + rl;
        int s = gr & (NS - 1);
        float m = mask[gr];
        const float* bnd = 0;
        if (s < 2)             bnd = start_t + s * 256;
        else if (s == len - 1) bnd = end_t;
        else if (s == len - 2) bnd = end_t + 256;

        float mx = -3.0e38f;
#pragma unroll
        for (int nf = 0; nf < 8; ++nf) {
            int col = wn * 64 + nf * 8 + tg * 2;
            float2 u = *(const float2*)(unary_score + (size_t)gr * NT + col);
            float q0 = u.x * m + acc[mf][nf][rsel * 2 + 0];
            float q1 = u.y * m + acc[mf][nf][rsel * 2 + 1];
            if (bnd) { q0 += bnd[col]; q1 += bnd[col + 1]; }
            q0 *= m; q1 *= m;
            acc[mf][nf][rsel * 2 + 0] = q0;
            acc[mf][nf][rsel * 2 + 1] = q1;
            mx = fmaxf(mx, fmaxf(q0, q1));
        }
        rowm[i] = mx;
    }

    if (mode == 2) {
#pragma unroll
        for (int i = 0; i < 4; ++i) {
            int mf = i >> 1, rsel = i & 1;
            int gr = m0 + wm * 32 + mf * 16 + g + rsel * 8;
#pragma unroll
            for (int nf = 0; nf < 8; ++nf) {
                int col = wn * 64 + nf * 8 + tg * 2;
                *(float2*)(out + (size_t)gr * NT + col) =
                    make_float2(acc[mf][nf][rsel * 2], acc[mf][nf][rsel * 2 + 1]);
            }
        }
        return;
    }

    // softmax across 256 cols: quad reduce (tg) then cross-warp (wn) via smem
    float* red0 = (float*)smem;          // [4][64]
    float* red1 = (float*)smem + 256;    // [4][64]

#pragma unroll
    for (int i = 0; i < 4; ++i) {
        float mx = rowm[i];
        mx = fmaxf(mx, __shfl_xor_sync(0xffffffffu, mx, 1));
        mx = fmaxf(mx, __shfl_xor_sync(0xffffffffu, mx, 2));
        rowm[i] = mx;
    }
    if (tg == 0) {
#pragma unroll
        for (int i = 0; i < 4; ++i) {
            int rl = wm * 32 + (i >> 1) * 16 + g + (i & 1) * 8;
            red0[wn * 64 + rl] = rowm[i];
        }
    }
    __syncthreads();
#pragma unroll
    for (int i = 0; i < 4; ++i) {
        int rl = wm * 32 + (i >> 1) * 16 + g + (i & 1) * 8;
        float mx = fmaxf(fmaxf(red0[rl], red0[64 + rl]),
                         fmaxf(red0[128 + rl], red0[192 + rl]));
        rowm[i] = mx;
        int mf = i >> 1, rsel = i & 1;
        float sum = 0.0f;
#pragma unroll
        for (int nf = 0; nf < 8; ++nf) {
            float e0 = __expf(acc[mf][nf][rsel * 2 + 0] - mx);
            float e1 = __expf(acc[mf][nf][rsel * 2 + 1] - mx);
            acc[mf][nf][rsel * 2 + 0] = e0;
            acc[mf][nf][rsel * 2 + 1] = e1;
            sum += e0 + e1;
        }
        sum += __shfl_xor_sync(0xffffffffu, sum, 1);
        sum += __shfl_xor_sync(0xffffffffu, sum, 2);
        rowv[i] = sum;
    }
    if (tg == 0) {
#pragma unroll
        for (int i = 0; i < 4; ++i) {
            int rl = wm * 32 + (i >> 1) * 16 + g + (i & 1) * 8;
            red1[wn * 64 + rl] = rowv[i];
        }
    }
    __syncthreads();
#pragma unroll
    for (int i = 0; i < 4; ++i) {
        int rl = wm * 32 + (i >> 1) * 16 + g + (i & 1) * 8;
        float sum = red1[rl] + red1[64 + rl] + red1[128 + rl] + red1[192 + rl];
        float rinv = __frcp_rn(sum);
        int mf = i >> 1, rsel = i & 1;
        int gr = m0 + rl;
#pragma unroll
        for (int nf = 0; nf < 8; ++nf) {
            int col = wn * 64 + nf * 8 + tg * 2;
            *(__half2*)(g_Ph + (size_t)gr * NT + col) =
                __floats2half2_rn(acc[mf][nf][rsel * 2] * rinv,
                                  acc[mf][nf][rsel * 2 + 1] * rinv);
        }
    }
}

// ---------------------------------------------------------------------------
// Input order: token_feats, unary_score, mask, transitions,
//              start_transitions, end_transitions, lengths
// ---------------------------------------------------------------------------
extern "C" void kernel_launch(void* const* d_in, const int* in_sizes, int n_in,
                              void* d_out, int out_size) {
    const float* unary   = (const float*)d_in[1];
    const float* mask    = (const float*)d_in[2];
    const float* trans   = (const float*)d_in[3];
    const float* start_t = (const float*)d_in[4];
    const float* end_t   = (const float*)d_in[5];
    const int*   lengths = (const int*)d_in[6];
    float* out = (float*)d_out;

    build_b_kernel<<<1024, 256>>>(trans);
    init_p_kernel<<<NBS / 8, 256>>>(unary, mask);

    for (int it = 0; it < 3; ++it) {
        int mode = (it == 2) ? 2 : 1;
        gemm_fused_kernel<<<NBS / 64, 256, GEMM_SMEM>>>(
            unary, mask, start_t, end_t, lengths, out, mode);
    }
}